// round 1
// baseline (speedup 1.0000x reference)
#include <cuda_runtime.h>
#include <math.h>

#define NN   50000
#define FIN  128
#define HIDD 256
#define NHD  4
#define DH   64
#define NE   400000
#define CATF 384
#define TTYP 2

// ---------------- scratch (device globals; no allocation allowed) ----------
static __device__ float g_z  [(size_t)NN*HIDD];
static __device__ float g_h  [(size_t)NN*HIDD];
static __device__ float g_x  [(size_t)NN*CATF];
static __device__ float g_scr[(size_t)NN*CATF];   // rst (256-wide) / agg (F-wide)
static __device__ float g_el [NN*NHD];
static __device__ float g_er [NN*NHD];
static __device__ float g_m  [NN*NHD];
static __device__ float g_den[NN*NHD];
static __device__ float g_e  [(size_t)NE*NHD];
static __device__ float g_ex [(size_t)NE*NHD];
static __device__ float g_stats[2*HIDD];
static __device__ float g_scale[HIDD];
static __device__ float g_shift[HIDD];

// ---------------- helpers --------------------------------------------------
__device__ __forceinline__ void red4(float* p, float a, float b, float c, float d) {
    asm volatile("red.global.add.v4.f32 [%0], {%1,%2,%3,%4};"
                 :: "l"(p), "f"(a), "f"(b), "f"(c), "f"(d) : "memory");
}

__device__ __forceinline__ void atomicMaxF(float* addr, float value) {
    if (value >= 0.f) atomicMax((int*)addr, __float_as_int(value));
    else              atomicMin((unsigned int*)addr, __float_as_uint(value));
}

__device__ __forceinline__ float lrelu(float v) { return v >= 0.f ? v : 0.2f * v; }

// ---------------- GEMM: C = act(A[M,K] @ W[K,Nout] + bias) -----------------
__global__ void gemm_kernel(const float* __restrict__ A, const float* __restrict__ W,
                            const float* __restrict__ bias, float* __restrict__ C,
                            int M, int K, int Nout, int relu_flag) {
    __shared__ float As[16][64];
    __shared__ float Bs[16][68];
    int tid = threadIdx.x;
    int tx = tid & 15, ty = tid >> 4;
    int rowBase = blockIdx.y * 64;
    int colBase = blockIdx.x * 64;
    float acc[4][4] = {};
    int am = tid >> 2;            // 0..63
    int ak = (tid & 3) * 4;       // 0,4,8,12
    int bk = tid >> 4;            // 0..15
    int bn = (tid & 15) * 4;      // 0..60
    for (int k0 = 0; k0 < K; k0 += 16) {
        int gm = rowBase + am;
        float4 av = make_float4(0.f, 0.f, 0.f, 0.f);
        if (gm < M) av = *(const float4*)(A + (size_t)gm * K + k0 + ak);
        As[ak  ][am] = av.x; As[ak+1][am] = av.y;
        As[ak+2][am] = av.z; As[ak+3][am] = av.w;
        float4 wv = *(const float4*)(W + (size_t)(k0 + bk) * Nout + colBase + bn);
        *(float4*)&Bs[bk][bn] = wv;
        __syncthreads();
#pragma unroll
        for (int kk = 0; kk < 16; kk++) {
            float a[4], b[4];
#pragma unroll
            for (int i = 0; i < 4; i++) a[i] = As[kk][ty * 4 + i];
#pragma unroll
            for (int j = 0; j < 4; j++) b[j] = Bs[kk][tx * 4 + j];
#pragma unroll
            for (int i = 0; i < 4; i++)
#pragma unroll
                for (int j = 0; j < 4; j++)
                    acc[i][j] += a[i] * b[j];
        }
        __syncthreads();
    }
#pragma unroll
    for (int i = 0; i < 4; i++) {
        int row = rowBase + ty * 4 + i;
        if (row >= M) continue;
#pragma unroll
        for (int j = 0; j < 4; j++) {
            int col = colBase + tx * 4 + j;
            float v = acc[i][j] + (bias ? bias[col] : 0.f);
            if (relu_flag) v = fmaxf(v, 0.f);
            C[(size_t)row * Nout + col] = v;
        }
    }
}

// ---------------- GAT pieces -----------------------------------------------
// el/er per (node, head): 1 block (128 thr) per node, warp h -> head h
__global__ void elz_kernel(const float* __restrict__ z,
                           const float* __restrict__ al, const float* __restrict__ ar) {
    int n = blockIdx.x;
    int w = threadIdx.x >> 5;
    int lane = threadIdx.x & 31;
    const float* zp = z + (size_t)n * HIDD + w * DH;
    float z0 = zp[lane], z1 = zp[lane + 32];
    float a0 = al[w * DH + lane], a1 = al[w * DH + lane + 32];
    float b0 = ar[w * DH + lane], b1 = ar[w * DH + lane + 32];
    float el = z0 * a0 + z1 * a1;
    float er = z0 * b0 + z1 * b1;
#pragma unroll
    for (int off = 16; off; off >>= 1) {
        el += __shfl_down_sync(0xffffffffu, el, off);
        er += __shfl_down_sync(0xffffffffu, er, off);
    }
    if (lane == 0) { g_el[n * NHD + w] = el; g_er[n * NHD + w] = er; }
}

__global__ void init_nh_kernel() {
    int i = blockIdx.x * blockDim.x + threadIdx.x;
    if (i < NN * NHD) { g_m[i] = -INFINITY; g_den[i] = 0.f; }
}

__global__ void edge_max_kernel(const int* __restrict__ src, const int* __restrict__ dst) {
    int e = blockIdx.x * blockDim.x + threadIdx.x;
    if (e >= NE) return;
    int s = src[e], d = dst[e];
    float4 elv = *(const float4*)(g_el + s * NHD);
    float4 erv = *(const float4*)(g_er + d * NHD);
    float4 ev;
    ev.x = lrelu(elv.x + erv.x);
    ev.y = lrelu(elv.y + erv.y);
    ev.z = lrelu(elv.z + erv.z);
    ev.w = lrelu(elv.w + erv.w);
    *(float4*)(g_e + (size_t)e * NHD) = ev;
    float* mp = g_m + d * NHD;
    atomicMaxF(mp + 0, ev.x);
    atomicMaxF(mp + 1, ev.y);
    atomicMaxF(mp + 2, ev.z);
    atomicMaxF(mp + 3, ev.w);
}

__global__ void fix_m_kernel() {
    int i = blockIdx.x * blockDim.x + threadIdx.x;
    if (i < NN * NHD) { if (g_m[i] < -3.0e38f) g_m[i] = 0.f; }
}

__global__ void edge_exp_kernel(const int* __restrict__ dst) {
    int e = blockIdx.x * blockDim.x + threadIdx.x;
    if (e >= NE) return;
    int d = dst[e];
    float4 ev = *(const float4*)(g_e + (size_t)e * NHD);
    float4 mv = *(const float4*)(g_m + d * NHD);
    float4 xv = make_float4(__expf(ev.x - mv.x), __expf(ev.y - mv.y),
                            __expf(ev.z - mv.z), __expf(ev.w - mv.w));
    *(float4*)(g_ex + (size_t)e * NHD) = xv;
    red4(g_den + d * NHD, xv.x, xv.y, xv.z, xv.w);
}

// warp per edge: scatter a * z[src] into rst[dst]
__global__ void edge_msg_kernel(const int* __restrict__ src, const int* __restrict__ dst,
                                const float* __restrict__ zin, float* __restrict__ rst) {
    int gt = blockIdx.x * blockDim.x + threadIdx.x;
    int e = gt >> 5;
    if (e >= NE) return;
    int lane = threadIdx.x & 31;
    int s = src[e], d = dst[e];
    float4 xv = *(const float4*)(g_ex + (size_t)e * NHD);
    float4 dv = *(const float4*)(g_den + d * NHD);
    float ax = xv.x / fmaxf(dv.x, 1e-9f);
    float ay = xv.y / fmaxf(dv.y, 1e-9f);
    float az = xv.z / fmaxf(dv.z, 1e-9f);
    float aw = xv.w / fmaxf(dv.w, 1e-9f);
    float a = (lane < 16) ? (lane < 8 ? ax : ay) : (lane < 24 ? az : aw);
    const float* zp = zin + (size_t)s * HIDD + lane * 8;
    float* rp = rst + (size_t)d * HIDD + lane * 8;
    float4 z0 = *(const float4*)zp;
    float4 z1 = *(const float4*)(zp + 4);
    red4(rp,     a * z0.x, a * z0.y, a * z0.z, a * z0.w);
    red4(rp + 4, a * z1.x, a * z1.y, a * z1.z, a * z1.w);
}

__global__ void gat_fin_kernel(const float* __restrict__ rst, const float* __restrict__ b,
                               float* __restrict__ hout) {
    int idx = blockIdx.x * blockDim.x + threadIdx.x;
    int i4 = idx * 4;
    if (i4 >= NN * HIDD) return;
    int c = i4 & (HIDD - 1);
    float4 r = *(const float4*)(rst + i4);
    float4 bb = *(const float4*)(b + c);
    float4 v;
    v.x = fmaxf(r.x + bb.x, 0.f);
    v.y = fmaxf(r.y + bb.y, 0.f);
    v.z = fmaxf(r.z + bb.z, 0.f);
    v.w = fmaxf(r.w + bb.w, 0.f);
    *(float4*)(hout + i4) = v;
}

// ---------------- concat + GIN pieces --------------------------------------
__global__ void concat_kernel(const float* __restrict__ h, const float* __restrict__ feats,
                              float* __restrict__ x) {
    int idx = blockIdx.x * blockDim.x + threadIdx.x;
    int i4 = idx * 4;
    if (i4 >= NN * CATF) return;
    int n = i4 / CATF;
    int c = i4 % CATF;
    float4 v = (c < HIDD) ? *(const float4*)(h + (size_t)n * HIDD + c)
                          : *(const float4*)(feats + (size_t)n * FIN + (c - HIDD));
    *(float4*)(x + i4) = v;
}

__global__ void edge_agg_kernel(const float* __restrict__ hin, const int* __restrict__ src,
                                const int* __restrict__ dst, float* __restrict__ agg, int F) {
    int gt = blockIdx.x * blockDim.x + threadIdx.x;
    int e = gt >> 5;
    if (e >= NE) return;
    int lane = threadIdx.x & 31;
    int s = src[e], d = dst[e];
    const float* hp = hin + (size_t)s * F;
    float* ap = agg + (size_t)d * F;
    for (int f = lane * 4; f < F; f += 128) {
        float4 v = *(const float4*)(hp + f);
        red4(ap + f, v.x, v.y, v.z, v.w);
    }
}

__global__ void combine_kernel(const float* __restrict__ hin, const float* __restrict__ agg,
                               const float* __restrict__ epsp, float* __restrict__ xout, int n) {
    int idx = blockIdx.x * blockDim.x + threadIdx.x;
    int i4 = idx * 4;
    if (i4 >= n) return;
    float e = 1.f + epsp[0];
    float4 hv = *(const float4*)(hin + i4);
    float4 av = *(const float4*)(agg + i4);
    float4 v = make_float4(e * hv.x + av.x, e * hv.y + av.y, e * hv.z + av.z, e * hv.w + av.w);
    *(float4*)(xout + i4) = v;
}

__global__ void stats_kernel(const float* __restrict__ y) {
    int col = threadIdx.x;
    float s = 0.f, s2 = 0.f;
    for (int r = blockIdx.x; r < NN; r += gridDim.x) {
        float v = y[(size_t)r * HIDD + col];
        s += v; s2 += v * v;
    }
    atomicAdd(&g_stats[col], s);
    atomicAdd(&g_stats[HIDD + col], s2);
}

__global__ void bnfin_kernel(const float* __restrict__ g1, const float* __restrict__ be1) {
    int c = threadIdx.x;
    float inv = 1.f / (float)NN;
    float mu = g_stats[c] * inv;
    float var = g_stats[HIDD + c] * inv - mu * mu;
    float rstd = rsqrtf(var + 1e-5f);
    float sc = g1[c] * rstd;
    g_scale[c] = sc;
    g_shift[c] = be1[c] - mu * sc;
}

__global__ void bnrelu_kernel(float* __restrict__ y) {
    int idx = blockIdx.x * blockDim.x + threadIdx.x;
    int i4 = idx * 4;
    if (i4 >= NN * HIDD) return;
    int c = i4 & (HIDD - 1);
    float4 v = *(const float4*)(y + i4);
    float4 sc = *(const float4*)(g_scale + c);
    float4 sh = *(const float4*)(g_shift + c);
    v.x = fmaxf(v.x * sc.x + sh.x, 0.f);
    v.y = fmaxf(v.y * sc.y + sh.y, 0.f);
    v.z = fmaxf(v.z * sc.z + sh.z, 0.f);
    v.w = fmaxf(v.w * sc.w + sh.w, 0.f);
    *(float4*)(y + i4) = v;
}

__global__ void out_write_kernel(const float* __restrict__ h, float* __restrict__ out, int toff) {
    int idx = blockIdx.x * blockDim.x + threadIdx.x;
    int i4 = idx * 4;
    if (i4 >= NN * HIDD) return;
    int n = i4 >> 8;
    int c = i4 & (HIDD - 1);
    float4 v = *(const float4*)(h + i4);
    *(float4*)(out + (size_t)n * (TTYP * HIDD) + toff + c) = v;
}

__global__ void zero_kernel(float* __restrict__ p, int n) {
    int idx = blockIdx.x * blockDim.x + threadIdx.x;
    int i4 = idx * 4;
    if (i4 >= n) return;
    *(float4*)(p + i4) = make_float4(0.f, 0.f, 0.f, 0.f);
}

// ---------------- host orchestration ---------------------------------------
static inline int blk4(int n) { return (n / 4 + 255) / 256; }

static void gemm(const float* A, const float* W, const float* b, float* C, int K, int relu) {
    dim3 grid(HIDD / 64, (NN + 63) / 64);
    gemm_kernel<<<grid, 256>>>(A, W, b, C, NN, K, HIDD, relu);
}

static void run_gat(const float* z, const float* al, const float* ar, const float* b,
                    const int* s, const int* d, float* rst, float* hout) {
    elz_kernel<<<NN, 128>>>(z, al, ar);
    init_nh_kernel<<<(NN * NHD + 255) / 256, 256>>>();
    edge_max_kernel<<<(NE + 255) / 256, 256>>>(s, d);
    fix_m_kernel<<<(NN * NHD + 255) / 256, 256>>>();
    edge_exp_kernel<<<(NE + 255) / 256, 256>>>(d);
    zero_kernel<<<blk4(NN * HIDD), 256>>>(rst, NN * HIDD);
    edge_msg_kernel<<<(NE * 32 + 255) / 256, 256>>>(s, d, z, rst);
    gat_fin_kernel<<<blk4(NN * HIDD), 256>>>(rst, b, hout);
}

static void run_gin(const float* hin, int F, const int* s, const int* d,
                    const float* eps, const float* W1, const float* b1,
                    const float* g1, const float* be1, const float* W2, const float* b2,
                    float* agg, float* xbuf, float* ybuf, float* hout, float* statsp) {
    zero_kernel<<<blk4(NN * F), 256>>>(agg, NN * F);
    edge_agg_kernel<<<(NE * 32 + 255) / 256, 256>>>(hin, s, d, agg, F);
    combine_kernel<<<blk4(NN * F), 256>>>(hin, agg, eps, xbuf, NN * F);
    gemm(xbuf, W1, b1, ybuf, F, 0);
    zero_kernel<<<1, 128>>>(statsp, 2 * HIDD);
    stats_kernel<<<512, HIDD>>>(ybuf);
    bnfin_kernel<<<1, HIDD>>>(g1, be1);
    bnrelu_kernel<<<blk4(NN * HIDD), 256>>>(ybuf);
    gemm(ybuf, W2, b2, hout, HIDD, 1);
}

extern "C" void kernel_launch(void* const* d_in, const int* in_sizes, int n_in,
                              void* d_out, int out_size) {
    const float* feats = (const float*)d_in[0];
    const int* src[2] = { (const int*)d_in[1], (const int*)d_in[3] };
    const int* dst[2] = { (const int*)d_in[2], (const int*)d_in[4] };
    const float* gat0_W   = (const float*)d_in[5];
    const float* gat0_al  = (const float*)d_in[6];
    const float* gat0_ar  = (const float*)d_in[7];
    const float* gat0_b   = (const float*)d_in[8];
    const float* gat1_W   = (const float*)d_in[9];
    const float* gat1_al  = (const float*)d_in[10];
    const float* gat1_ar  = (const float*)d_in[11];
    const float* gat1_b   = (const float*)d_in[12];
    const float* gin0_eps = (const float*)d_in[13];
    const float* gin0_W1  = (const float*)d_in[14];
    const float* gin0_b1  = (const float*)d_in[15];
    const float* gin0_g1  = (const float*)d_in[16];
    const float* gin0_be1 = (const float*)d_in[17];
    const float* gin0_W2  = (const float*)d_in[18];
    const float* gin0_b2  = (const float*)d_in[19];
    const float* gin1_eps = (const float*)d_in[20];
    const float* gin1_W1  = (const float*)d_in[21];
    const float* gin1_b1  = (const float*)d_in[22];
    const float* gin1_g1  = (const float*)d_in[23];
    const float* gin1_be1 = (const float*)d_in[24];
    const float* gin1_W2  = (const float*)d_in[25];
    const float* gin1_b2  = (const float*)d_in[26];
    float* out = (float*)d_out;

    float *z, *h, *x, *scr, *statsp;
    cudaGetSymbolAddress((void**)&z, g_z);
    cudaGetSymbolAddress((void**)&h, g_h);
    cudaGetSymbolAddress((void**)&x, g_x);
    cudaGetSymbolAddress((void**)&scr, g_scr);
    cudaGetSymbolAddress((void**)&statsp, g_stats);

    for (int t = 0; t < TTYP; t++) {
        // GAT layer 0: z = feats @ W (no bias inside projection)
        gemm(feats, gat0_W + (size_t)t * FIN * HIDD, nullptr, z, FIN, 0);
        run_gat(z, gat0_al + t * NHD * DH, gat0_ar + t * NHD * DH,
                gat0_b + t * HIDD, src[t], dst[t], scr, h);
        // GAT layer 1
        gemm(h, gat1_W + (size_t)t * HIDD * HIDD, nullptr, z, HIDD, 0);
        run_gat(z, gat1_al + t * NHD * DH, gat1_ar + t * NHD * DH,
                gat1_b + t * HIDD, src[t], dst[t], scr, h);
        // skip-concat
        concat_kernel<<<blk4(NN * CATF), 256>>>(h, feats, x);
        // GIN layer 0 (F = 384)
        run_gin(x, CATF, src[t], dst[t], gin0_eps + t,
                gin0_W1 + (size_t)t * CATF * HIDD, gin0_b1 + t * HIDD,
                gin0_g1 + t * HIDD, gin0_be1 + t * HIDD,
                gin0_W2 + (size_t)t * HIDD * HIDD, gin0_b2 + t * HIDD,
                scr, x, z, h, statsp);
        // GIN layer 1 (F = 256)
        run_gin(h, HIDD, src[t], dst[t], gin1_eps + t,
                gin1_W1 + (size_t)t * HIDD * HIDD, gin1_b1 + t * HIDD,
                gin1_g1 + t * HIDD, gin1_be1 + t * HIDD,
                gin1_W2 + (size_t)t * HIDD * HIDD, gin1_b2 + t * HIDD,
                scr, x, z, h, statsp);
        // write this type's 256-column block of the [N, 512] output
        out_write_kernel<<<blk4(NN * HIDD), 256>>>(h, out, t * HIDD);
    }
}

// round 2
// speedup vs baseline: 1.0821x; 1.0821x over previous
#include <cuda_runtime.h>
#include <math.h>

#define NN   50000
#define FIN  128
#define HIDD 256
#define NHD  4
#define DH   64
#define NE   400000
#define CATF 384
#define TTYP 2

#define BM 128
#define BN 128
#define BK 16

// ---------------- scratch (device globals; no allocation allowed) ----------
static __device__ float g_z  [(size_t)NN*HIDD];
static __device__ float g_h  [(size_t)NN*HIDD];
static __device__ float g_x  [(size_t)NN*CATF];
static __device__ float g_scr[(size_t)NN*CATF];   // rst (256-wide) / agg (F-wide)
static __device__ float g_el [NN*NHD];
static __device__ float g_er [NN*NHD];
static __device__ float g_m  [NN*NHD];
static __device__ float g_den[NN*NHD];
static __device__ float g_e  [(size_t)NE*NHD];
static __device__ float g_ex [(size_t)NE*NHD];
static __device__ float g_stats[2*HIDD];
static __device__ float g_scale[HIDD];
static __device__ float g_shift[HIDD];

// ---------------- helpers --------------------------------------------------
__device__ __forceinline__ void red4(float* p, float a, float b, float c, float d) {
    asm volatile("red.global.add.v4.f32 [%0], {%1,%2,%3,%4};"
                 :: "l"(p), "f"(a), "f"(b), "f"(c), "f"(d) : "memory");
}

__device__ __forceinline__ void atomicMaxF(float* addr, float value) {
    if (value >= 0.f) atomicMax((int*)addr, __float_as_int(value));
    else              atomicMin((unsigned int*)addr, __float_as_uint(value));
}

__device__ __forceinline__ float lrelu(float v) { return v >= 0.f ? v : 0.2f * v; }

// ---------------- GEMM: C = act(A[M,K] @ W[K,Nout] + bias) -----------------
// 128x128 tile, 8x8 per thread, BK=16, double-buffered smem.
__global__ __launch_bounds__(256, 2)
void gemm_kernel(const float* __restrict__ A, const float* __restrict__ W,
                 const float* __restrict__ bias, float* __restrict__ C,
                 int M, int K, int Nout, int ldc, int coff, int relu_flag) {
    __shared__ float As[2][BK][BM + 4];
    __shared__ float Bs[2][BK][BN];
    int tid = threadIdx.x;
    int rowBase = blockIdx.y * BM;
    int colBase = blockIdx.x * BN;

    int aRow0 = tid >> 2;          // 0..63
    int aCol  = (tid & 3) * 4;     // 0,4,8,12
    int bRow0 = tid >> 5;          // 0..7
    int bCol  = (tid & 31) * 4;    // 0..124

    int tx = tid & 15, ty = tid >> 4;

    float acc[8][8] = {};

    int nk = K / BK;

    // ---- prologue: load tile 0 ----
    {
#pragma unroll
        for (int r = 0; r < 2; r++) {
            int row = rowBase + aRow0 + r * 64;
            float4 v = make_float4(0.f, 0.f, 0.f, 0.f);
            if (row < M) v = *(const float4*)(A + (size_t)row * K + aCol);
            As[0][aCol    ][aRow0 + r * 64] = v.x;
            As[0][aCol + 1][aRow0 + r * 64] = v.y;
            As[0][aCol + 2][aRow0 + r * 64] = v.z;
            As[0][aCol + 3][aRow0 + r * 64] = v.w;
        }
#pragma unroll
        for (int r = 0; r < 2; r++) {
            *(float4*)&Bs[0][bRow0 + r * 8][bCol] =
                *(const float4*)(W + (size_t)(bRow0 + r * 8) * Nout + colBase + bCol);
        }
    }
    __syncthreads();

    for (int kt = 0; kt < nk; kt++) {
        int cur = kt & 1;
        if (kt + 1 < nk) {
            int k0 = (kt + 1) * BK;
#pragma unroll
            for (int r = 0; r < 2; r++) {
                int row = rowBase + aRow0 + r * 64;
                float4 v = make_float4(0.f, 0.f, 0.f, 0.f);
                if (row < M) v = *(const float4*)(A + (size_t)row * K + k0 + aCol);
                As[cur ^ 1][aCol    ][aRow0 + r * 64] = v.x;
                As[cur ^ 1][aCol + 1][aRow0 + r * 64] = v.y;
                As[cur ^ 1][aCol + 2][aRow0 + r * 64] = v.z;
                As[cur ^ 1][aCol + 3][aRow0 + r * 64] = v.w;
            }
#pragma unroll
            for (int r = 0; r < 2; r++) {
                *(float4*)&Bs[cur ^ 1][bRow0 + r * 8][bCol] =
                    *(const float4*)(W + (size_t)(k0 + bRow0 + r * 8) * Nout + colBase + bCol);
            }
        }
#pragma unroll
        for (int kk = 0; kk < BK; kk++) {
            float a[8], b[8];
            *(float4*)&a[0] = *(const float4*)&As[cur][kk][ty * 8];
            *(float4*)&a[4] = *(const float4*)&As[cur][kk][ty * 8 + 4];
            *(float4*)&b[0] = *(const float4*)&Bs[cur][kk][tx * 8];
            *(float4*)&b[4] = *(const float4*)&Bs[cur][kk][tx * 8 + 4];
#pragma unroll
            for (int i = 0; i < 8; i++)
#pragma unroll
                for (int j = 0; j < 8; j++)
                    acc[i][j] += a[i] * b[j];
        }
        __syncthreads();
    }

    // ---- epilogue ----
    float bb[8];
    if (bias) {
        *(float4*)&bb[0] = *(const float4*)(bias + colBase + tx * 8);
        *(float4*)&bb[4] = *(const float4*)(bias + colBase + tx * 8 + 4);
    } else {
#pragma unroll
        for (int j = 0; j < 8; j++) bb[j] = 0.f;
    }
#pragma unroll
    for (int i = 0; i < 8; i++) {
        int row = rowBase + ty * 8 + i;
        if (row >= M) continue;
        float* crow = C + (size_t)row * ldc + coff + colBase + tx * 8;
#pragma unroll
        for (int j = 0; j < 8; j += 4) {
            float4 v;
            v.x = acc[i][j + 0] + bb[j + 0];
            v.y = acc[i][j + 1] + bb[j + 1];
            v.z = acc[i][j + 2] + bb[j + 2];
            v.w = acc[i][j + 3] + bb[j + 3];
            if (relu_flag) {
                v.x = fmaxf(v.x, 0.f); v.y = fmaxf(v.y, 0.f);
                v.z = fmaxf(v.z, 0.f); v.w = fmaxf(v.w, 0.f);
            }
            *(float4*)(crow + j) = v;
        }
    }
}

// ---------------- GAT pieces -----------------------------------------------
__global__ void elz_kernel(const float* __restrict__ z,
                           const float* __restrict__ al, const float* __restrict__ ar) {
    int n = blockIdx.x;
    int w = threadIdx.x >> 5;
    int lane = threadIdx.x & 31;
    const float* zp = z + (size_t)n * HIDD + w * DH;
    float z0 = zp[lane], z1 = zp[lane + 32];
    float a0 = al[w * DH + lane], a1 = al[w * DH + lane + 32];
    float b0 = ar[w * DH + lane], b1 = ar[w * DH + lane + 32];
    float el = z0 * a0 + z1 * a1;
    float er = z0 * b0 + z1 * b1;
#pragma unroll
    for (int off = 16; off; off >>= 1) {
        el += __shfl_down_sync(0xffffffffu, el, off);
        er += __shfl_down_sync(0xffffffffu, er, off);
    }
    if (lane == 0) { g_el[n * NHD + w] = el; g_er[n * NHD + w] = er; }
}

__global__ void init_nh_kernel() {
    int i = blockIdx.x * blockDim.x + threadIdx.x;
    if (i < NN * NHD) { g_m[i] = -INFINITY; g_den[i] = 0.f; }
}

__global__ void edge_max_kernel(const int* __restrict__ src, const int* __restrict__ dst) {
    int e = blockIdx.x * blockDim.x + threadIdx.x;
    if (e >= NE) return;
    int s = src[e], d = dst[e];
    float4 elv = *(const float4*)(g_el + s * NHD);
    float4 erv = *(const float4*)(g_er + d * NHD);
    float4 ev;
    ev.x = lrelu(elv.x + erv.x);
    ev.y = lrelu(elv.y + erv.y);
    ev.z = lrelu(elv.z + erv.z);
    ev.w = lrelu(elv.w + erv.w);
    *(float4*)(g_e + (size_t)e * NHD) = ev;
    float* mp = g_m + d * NHD;
    atomicMaxF(mp + 0, ev.x);
    atomicMaxF(mp + 1, ev.y);
    atomicMaxF(mp + 2, ev.z);
    atomicMaxF(mp + 3, ev.w);
}

__global__ void edge_exp_kernel(const int* __restrict__ dst) {
    int e = blockIdx.x * blockDim.x + threadIdx.x;
    if (e >= NE) return;
    int d = dst[e];
    float4 ev = *(const float4*)(g_e + (size_t)e * NHD);
    float4 mv = *(const float4*)(g_m + d * NHD);
    float4 xv = make_float4(__expf(ev.x - mv.x), __expf(ev.y - mv.y),
                            __expf(ev.z - mv.z), __expf(ev.w - mv.w));
    *(float4*)(g_ex + (size_t)e * NHD) = xv;
    red4(g_den + d * NHD, xv.x, xv.y, xv.z, xv.w);
}

// warp per edge: scatter a * z[src] into rst[dst]
__global__ void edge_msg_kernel(const int* __restrict__ src, const int* __restrict__ dst,
                                const float* __restrict__ zin, float* __restrict__ rst) {
    int gt = blockIdx.x * blockDim.x + threadIdx.x;
    int e = gt >> 5;
    if (e >= NE) return;
    int lane = threadIdx.x & 31;
    int s = src[e], d = dst[e];
    float4 xv = *(const float4*)(g_ex + (size_t)e * NHD);
    float4 dv = *(const float4*)(g_den + d * NHD);
    float ax = xv.x / fmaxf(dv.x, 1e-9f);
    float ay = xv.y / fmaxf(dv.y, 1e-9f);
    float az = xv.z / fmaxf(dv.z, 1e-9f);
    float aw = xv.w / fmaxf(dv.w, 1e-9f);
    float a = (lane < 16) ? (lane < 8 ? ax : ay) : (lane < 24 ? az : aw);
    const float* zp = zin + (size_t)s * HIDD + lane * 8;
    float* rp = rst + (size_t)d * HIDD + lane * 8;
    float4 z0 = *(const float4*)zp;
    float4 z1 = *(const float4*)(zp + 4);
    red4(rp,     a * z0.x, a * z0.y, a * z0.z, a * z0.w);
    red4(rp + 4, a * z1.x, a * z1.y, a * z1.z, a * z1.w);
}

__global__ void gat_fin_kernel(const float* __restrict__ rst, const float* __restrict__ b,
                               float* __restrict__ hout) {
    int idx = blockIdx.x * blockDim.x + threadIdx.x;
    int i4 = idx * 4;
    if (i4 >= NN * HIDD) return;
    int c = i4 & (HIDD - 1);
    float4 r = *(const float4*)(rst + i4);
    float4 bb = *(const float4*)(b + c);
    float4 v;
    v.x = fmaxf(r.x + bb.x, 0.f);
    v.y = fmaxf(r.y + bb.y, 0.f);
    v.z = fmaxf(r.z + bb.z, 0.f);
    v.w = fmaxf(r.w + bb.w, 0.f);
    *(float4*)(hout + i4) = v;
}

// ---------------- concat + GIN pieces --------------------------------------
__global__ void concat_kernel(const float* __restrict__ h, const float* __restrict__ feats,
                              float* __restrict__ x) {
    int idx = blockIdx.x * blockDim.x + threadIdx.x;
    int i4 = idx * 4;
    if (i4 >= NN * CATF) return;
    int n = i4 / CATF;
    int c = i4 % CATF;
    float4 v = (c < HIDD) ? *(const float4*)(h + (size_t)n * HIDD + c)
                          : *(const float4*)(feats + (size_t)n * FIN + (c - HIDD));
    *(float4*)(x + i4) = v;
}

__global__ void edge_agg_kernel(const float* __restrict__ hin, const int* __restrict__ src,
                                const int* __restrict__ dst, float* __restrict__ agg, int F) {
    int gt = blockIdx.x * blockDim.x + threadIdx.x;
    int e = gt >> 5;
    if (e >= NE) return;
    int lane = threadIdx.x & 31;
    int s = src[e], d = dst[e];
    const float* hp = hin + (size_t)s * F;
    float* ap = agg + (size_t)d * F;
    for (int f = lane * 4; f < F; f += 128) {
        float4 v = *(const float4*)(hp + f);
        red4(ap + f, v.x, v.y, v.z, v.w);
    }
}

__global__ void combine_kernel(const float* __restrict__ hin, const float* __restrict__ agg,
                               const float* __restrict__ epsp, float* __restrict__ xout, int n) {
    int idx = blockIdx.x * blockDim.x + threadIdx.x;
    int i4 = idx * 4;
    if (i4 >= n) return;
    float e = 1.f + epsp[0];
    float4 hv = *(const float4*)(hin + i4);
    float4 av = *(const float4*)(agg + i4);
    float4 v = make_float4(e * hv.x + av.x, e * hv.y + av.y, e * hv.z + av.z, e * hv.w + av.w);
    *(float4*)(xout + i4) = v;
}

__global__ void stats_kernel(const float* __restrict__ y) {
    int col = threadIdx.x;
    float s = 0.f, s2 = 0.f;
    for (int r = blockIdx.x; r < NN; r += gridDim.x) {
        float v = y[(size_t)r * HIDD + col];
        s += v; s2 += v * v;
    }
    atomicAdd(&g_stats[col], s);
    atomicAdd(&g_stats[HIDD + col], s2);
}

__global__ void bnfin_kernel(const float* __restrict__ g1, const float* __restrict__ be1) {
    int c = threadIdx.x;
    float inv = 1.f / (float)NN;
    float mu = g_stats[c] * inv;
    float var = g_stats[HIDD + c] * inv - mu * mu;
    float rstd = rsqrtf(var + 1e-5f);
    float sc = g1[c] * rstd;
    g_scale[c] = sc;
    g_shift[c] = be1[c] - mu * sc;
}

__global__ void bnrelu_kernel(float* __restrict__ y) {
    int idx = blockIdx.x * blockDim.x + threadIdx.x;
    int i4 = idx * 4;
    if (i4 >= NN * HIDD) return;
    int c = i4 & (HIDD - 1);
    float4 v = *(const float4*)(y + i4);
    float4 sc = *(const float4*)(g_scale + c);
    float4 sh = *(const float4*)(g_shift + c);
    v.x = fmaxf(v.x * sc.x + sh.x, 0.f);
    v.y = fmaxf(v.y * sc.y + sh.y, 0.f);
    v.z = fmaxf(v.z * sc.z + sh.z, 0.f);
    v.w = fmaxf(v.w * sc.w + sh.w, 0.f);
    *(float4*)(y + i4) = v;
}

__global__ void zero_kernel(float* __restrict__ p, int n) {
    int idx = blockIdx.x * blockDim.x + threadIdx.x;
    int i4 = idx * 4;
    if (i4 >= n) return;
    *(float4*)(p + i4) = make_float4(0.f, 0.f, 0.f, 0.f);
}

// ---------------- host orchestration ---------------------------------------
static inline int blk4(int n) { return (n / 4 + 255) / 256; }

static void gemm(const float* A, const float* W, const float* b, float* C,
                 int K, int relu, int ldc = HIDD, int coff = 0) {
    dim3 grid(HIDD / BN, (NN + BM - 1) / BM);
    gemm_kernel<<<grid, 256>>>(A, W, b, C, NN, K, HIDD, ldc, coff, relu);
}

static void run_gat(const float* z, const float* al, const float* ar, const float* b,
                    const int* s, const int* d, float* rst, float* hout) {
    elz_kernel<<<NN, 128>>>(z, al, ar);
    init_nh_kernel<<<(NN * NHD + 255) / 256, 256>>>();
    edge_max_kernel<<<(NE + 255) / 256, 256>>>(s, d);
    edge_exp_kernel<<<(NE + 255) / 256, 256>>>(d);
    zero_kernel<<<blk4(NN * HIDD), 256>>>(rst, NN * HIDD);
    edge_msg_kernel<<<(NE * 32 + 255) / 256, 256>>>(s, d, z, rst);
    gat_fin_kernel<<<blk4(NN * HIDD), 256>>>(rst, b, hout);
}

static void run_gin(const float* hin, int F, const int* s, const int* d,
                    const float* eps, const float* W1, const float* b1,
                    const float* g1, const float* be1, const float* W2, const float* b2,
                    float* agg, float* xbuf, float* ybuf, float* hout, float* statsp,
                    int ldc, int coff) {
    zero_kernel<<<blk4(NN * F), 256>>>(agg, NN * F);
    edge_agg_kernel<<<(NE * 32 + 255) / 256, 256>>>(hin, s, d, agg, F);
    combine_kernel<<<blk4(NN * F), 256>>>(hin, agg, eps, xbuf, NN * F);
    gemm(xbuf, W1, b1, ybuf, F, 0);
    zero_kernel<<<1, 128>>>(statsp, 2 * HIDD);
    stats_kernel<<<512, HIDD>>>(ybuf);
    bnfin_kernel<<<1, HIDD>>>(g1, be1);
    bnrelu_kernel<<<blk4(NN * HIDD), 256>>>(ybuf);
    gemm(ybuf, W2, b2, hout, HIDD, 1, ldc, coff);
}

extern "C" void kernel_launch(void* const* d_in, const int* in_sizes, int n_in,
                              void* d_out, int out_size) {
    const float* feats = (const float*)d_in[0];
    const int* src[2] = { (const int*)d_in[1], (const int*)d_in[3] };
    const int* dst[2] = { (const int*)d_in[2], (const int*)d_in[4] };
    const float* gat0_W   = (const float*)d_in[5];
    const float* gat0_al  = (const float*)d_in[6];
    const float* gat0_ar  = (const float*)d_in[7];
    const float* gat0_b   = (const float*)d_in[8];
    const float* gat1_W   = (const float*)d_in[9];
    const float* gat1_al  = (const float*)d_in[10];
    const float* gat1_ar  = (const float*)d_in[11];
    const float* gat1_b   = (const float*)d_in[12];
    const float* gin0_eps = (const float*)d_in[13];
    const float* gin0_W1  = (const float*)d_in[14];
    const float* gin0_b1  = (const float*)d_in[15];
    const float* gin0_g1  = (const float*)d_in[16];
    const float* gin0_be1 = (const float*)d_in[17];
    const float* gin0_W2  = (const float*)d_in[18];
    const float* gin0_b2  = (const float*)d_in[19];
    const float* gin1_eps = (const float*)d_in[20];
    const float* gin1_W1  = (const float*)d_in[21];
    const float* gin1_b1  = (const float*)d_in[22];
    const float* gin1_g1  = (const float*)d_in[23];
    const float* gin1_be1 = (const float*)d_in[24];
    const float* gin1_W2  = (const float*)d_in[25];
    const float* gin1_b2  = (const float*)d_in[26];
    float* out = (float*)d_out;

    float *z, *h, *x, *scr, *statsp;
    cudaGetSymbolAddress((void**)&z, g_z);
    cudaGetSymbolAddress((void**)&h, g_h);
    cudaGetSymbolAddress((void**)&x, g_x);
    cudaGetSymbolAddress((void**)&scr, g_scr);
    cudaGetSymbolAddress((void**)&statsp, g_stats);

    for (int t = 0; t < TTYP; t++) {
        // GAT layer 0: z = feats @ W
        gemm(feats, gat0_W + (size_t)t * FIN * HIDD, nullptr, z, FIN, 0);
        run_gat(z, gat0_al + t * NHD * DH, gat0_ar + t * NHD * DH,
                gat0_b + t * HIDD, src[t], dst[t], scr, h);
        // GAT layer 1
        gemm(h, gat1_W + (size_t)t * HIDD * HIDD, nullptr, z, HIDD, 0);
        run_gat(z, gat1_al + t * NHD * DH, gat1_ar + t * NHD * DH,
                gat1_b + t * HIDD, src[t], dst[t], scr, h);
        // skip-concat
        concat_kernel<<<blk4(NN * CATF), 256>>>(h, feats, x);
        // GIN layer 0 (F = 384)
        run_gin(x, CATF, src[t], dst[t], gin0_eps + t,
                gin0_W1 + (size_t)t * CATF * HIDD, gin0_b1 + t * HIDD,
                gin0_g1 + t * HIDD, gin0_be1 + t * HIDD,
                gin0_W2 + (size_t)t * HIDD * HIDD, gin0_b2 + t * HIDD,
                scr, x, z, h, statsp, HIDD, 0);
        // GIN layer 1 (F = 256) — final GEMM writes straight into the strided output
        run_gin(h, HIDD, src[t], dst[t], gin1_eps + t,
                gin1_W1 + (size_t)t * HIDD * HIDD, gin1_b1 + t * HIDD,
                gin1_g1 + t * HIDD, gin1_be1 + t * HIDD,
                gin1_W2 + (size_t)t * HIDD * HIDD, gin1_b2 + t * HIDD,
                scr, x, z, out, statsp, TTYP * HIDD, t * HIDD);
    }
}

// round 3
// speedup vs baseline: 1.0890x; 1.0064x over previous
#include <cuda_runtime.h>
#include <math.h>

#define NN   50000
#define FIN  128
#define HIDD 256
#define NHD  4
#define DH   64
#define NE   400000
#define CATF 384
#define TTYP 2

#define BM 128
#define BN 128
#define BK 16

// ---------------- scratch (device globals; no allocation allowed) ----------
static __device__ float g_z  [(size_t)NN*HIDD];
static __device__ float g_h  [(size_t)NN*HIDD];
static __device__ float g_x  [(size_t)NN*CATF];
static __device__ float g_scr[(size_t)NN*CATF];   // rst (256-wide) / agg (F-wide)
static __device__ float g_el [NN*NHD];
static __device__ float g_er [NN*NHD];
static __device__ float g_m  [NN*NHD];
static __device__ float g_den[NN*NHD];
static __device__ float g_e  [(size_t)NE*NHD];
static __device__ float g_ex [(size_t)NE*NHD];
static __device__ float g_stats[2*HIDD];
static __device__ float g_scale[HIDD];
static __device__ float g_shift[HIDD];

// ---------------- helpers --------------------------------------------------
__device__ __forceinline__ void red4(float* p, float a, float b, float c, float d) {
    asm volatile("red.global.add.v4.f32 [%0], {%1,%2,%3,%4};"
                 :: "l"(p), "f"(a), "f"(b), "f"(c), "f"(d) : "memory");
}

__device__ __forceinline__ void atomicMaxF(float* addr, float value) {
    if (value >= 0.f) atomicMax((int*)addr, __float_as_int(value));
    else              atomicMin((unsigned int*)addr, __float_as_uint(value));
}

__device__ __forceinline__ float lrelu(float v) { return v >= 0.f ? v : 0.2f * v; }

// ---------------- GEMM: C = act(A[M,K] @ W[K,Nout] + bias) -----------------
// 128x128 tile, 8x8 per thread, BK=16, double-buffered smem,
// inner product via packed fma.rn.f32x2 (2 FMA per issue on sm_103a).
__global__ __launch_bounds__(256, 2)
void gemm_kernel(const float* __restrict__ A, const float* __restrict__ W,
                 const float* __restrict__ bias, float* __restrict__ C,
                 int M, int K, int Nout, int ldc, int coff, int relu_flag) {
    __shared__ float As[2][BK][BM + 4];
    __shared__ float Bs[2][BK][BN];
    int tid = threadIdx.x;
    int rowBase = blockIdx.y * BM;
    int colBase = blockIdx.x * BN;

    int aRow0 = tid >> 2;          // 0..63
    int aCol  = (tid & 3) * 4;     // 0,4,8,12
    int bRow0 = tid >> 5;          // 0..7
    int bCol  = (tid & 31) * 4;    // 0..124

    int tx = tid & 15, ty = tid >> 4;

    // acc[i][j2] = packed pair (C[i][2*j2], C[i][2*j2+1])
    unsigned long long acc[8][4];
#pragma unroll
    for (int i = 0; i < 8; i++)
#pragma unroll
        for (int j = 0; j < 4; j++) acc[i][j] = 0ull;

    int nk = K / BK;

    // ---- prologue: load tile 0 ----
    {
#pragma unroll
        for (int r = 0; r < 2; r++) {
            int row = rowBase + aRow0 + r * 64;
            float4 v = make_float4(0.f, 0.f, 0.f, 0.f);
            if (row < M) v = *(const float4*)(A + (size_t)row * K + aCol);
            As[0][aCol    ][aRow0 + r * 64] = v.x;
            As[0][aCol + 1][aRow0 + r * 64] = v.y;
            As[0][aCol + 2][aRow0 + r * 64] = v.z;
            As[0][aCol + 3][aRow0 + r * 64] = v.w;
        }
#pragma unroll
        for (int r = 0; r < 2; r++) {
            *(float4*)&Bs[0][bRow0 + r * 8][bCol] =
                *(const float4*)(W + (size_t)(bRow0 + r * 8) * Nout + colBase + bCol);
        }
    }
    __syncthreads();

    for (int kt = 0; kt < nk; kt++) {
        int cur = kt & 1;
        if (kt + 1 < nk) {
            int k0 = (kt + 1) * BK;
#pragma unroll
            for (int r = 0; r < 2; r++) {
                int row = rowBase + aRow0 + r * 64;
                float4 v = make_float4(0.f, 0.f, 0.f, 0.f);
                if (row < M) v = *(const float4*)(A + (size_t)row * K + k0 + aCol);
                As[cur ^ 1][aCol    ][aRow0 + r * 64] = v.x;
                As[cur ^ 1][aCol + 1][aRow0 + r * 64] = v.y;
                As[cur ^ 1][aCol + 2][aRow0 + r * 64] = v.z;
                As[cur ^ 1][aCol + 3][aRow0 + r * 64] = v.w;
            }
#pragma unroll
            for (int r = 0; r < 2; r++) {
                *(float4*)&Bs[cur ^ 1][bRow0 + r * 8][bCol] =
                    *(const float4*)(W + (size_t)(k0 + bRow0 + r * 8) * Nout + colBase + bCol);
            }
        }
#pragma unroll
        for (int kk = 0; kk < BK; kk++) {
            unsigned int a[8];
            *(uint4*)&a[0] = *(const uint4*)&As[cur][kk][ty * 8];
            *(uint4*)&a[4] = *(const uint4*)&As[cur][kk][ty * 8 + 4];
            unsigned long long b2[4];
            {
                ulonglong2 t0 = *(const ulonglong2*)&Bs[cur][kk][tx * 8];
                ulonglong2 t1 = *(const ulonglong2*)&Bs[cur][kk][tx * 8 + 4];
                b2[0] = t0.x; b2[1] = t0.y; b2[2] = t1.x; b2[3] = t1.y;
            }
#pragma unroll
            for (int i = 0; i < 8; i++) {
                unsigned long long ad;
                asm("mov.b64 %0, {%1, %1};" : "=l"(ad) : "r"(a[i]));
#pragma unroll
                for (int j = 0; j < 4; j++) {
                    asm("fma.rn.f32x2 %0, %1, %2, %0;"
                        : "+l"(acc[i][j]) : "l"(ad), "l"(b2[j]));
                }
            }
        }
        __syncthreads();
    }

    // ---- epilogue ----
    float bb[8];
    if (bias) {
        *(float4*)&bb[0] = *(const float4*)(bias + colBase + tx * 8);
        *(float4*)&bb[4] = *(const float4*)(bias + colBase + tx * 8 + 4);
    } else {
#pragma unroll
        for (int j = 0; j < 8; j++) bb[j] = 0.f;
    }
#pragma unroll
    for (int i = 0; i < 8; i++) {
        int row = rowBase + ty * 8 + i;
        if (row >= M) continue;
        float* crow = C + (size_t)row * ldc + coff + colBase + tx * 8;
#pragma unroll
        for (int j = 0; j < 8; j += 4) {
            unsigned int lo0, hi0, lo1, hi1;
            asm("mov.b64 {%0, %1}, %2;" : "=r"(lo0), "=r"(hi0) : "l"(acc[i][j / 2]));
            asm("mov.b64 {%0, %1}, %2;" : "=r"(lo1), "=r"(hi1) : "l"(acc[i][j / 2 + 1]));
            float4 v;
            v.x = __uint_as_float(lo0) + bb[j + 0];
            v.y = __uint_as_float(hi0) + bb[j + 1];
            v.z = __uint_as_float(lo1) + bb[j + 2];
            v.w = __uint_as_float(hi1) + bb[j + 3];
            if (relu_flag) {
                v.x = fmaxf(v.x, 0.f); v.y = fmaxf(v.y, 0.f);
                v.z = fmaxf(v.z, 0.f); v.w = fmaxf(v.w, 0.f);
            }
            *(float4*)(crow + j) = v;
        }
    }
}

// ---------------- GAT pieces -----------------------------------------------
__global__ void elz_kernel(const float* __restrict__ z,
                           const float* __restrict__ al, const float* __restrict__ ar) {
    int n = blockIdx.x;
    int w = threadIdx.x >> 5;
    int lane = threadIdx.x & 31;
    const float* zp = z + (size_t)n * HIDD + w * DH;
    float z0 = zp[lane], z1 = zp[lane + 32];
    float a0 = al[w * DH + lane], a1 = al[w * DH + lane + 32];
    float b0 = ar[w * DH + lane], b1 = ar[w * DH + lane + 32];
    float el = z0 * a0 + z1 * a1;
    float er = z0 * b0 + z1 * b1;
#pragma unroll
    for (int off = 16; off; off >>= 1) {
        el += __shfl_down_sync(0xffffffffu, el, off);
        er += __shfl_down_sync(0xffffffffu, er, off);
    }
    if (lane == 0) { g_el[n * NHD + w] = el; g_er[n * NHD + w] = er; }
}

__global__ void init_nh_kernel() {
    int i = blockIdx.x * blockDim.x + threadIdx.x;
    if (i < NN * NHD) { g_m[i] = -INFINITY; g_den[i] = 0.f; }
}

__global__ void edge_max_kernel(const int* __restrict__ src, const int* __restrict__ dst) {
    int e = blockIdx.x * blockDim.x + threadIdx.x;
    if (e >= NE) return;
    int s = src[e], d = dst[e];
    float4 elv = *(const float4*)(g_el + s * NHD);
    float4 erv = *(const float4*)(g_er + d * NHD);
    float4 ev;
    ev.x = lrelu(elv.x + erv.x);
    ev.y = lrelu(elv.y + erv.y);
    ev.z = lrelu(elv.z + erv.z);
    ev.w = lrelu(elv.w + erv.w);
    *(float4*)(g_e + (size_t)e * NHD) = ev;
    float* mp = g_m + d * NHD;
    atomicMaxF(mp + 0, ev.x);
    atomicMaxF(mp + 1, ev.y);
    atomicMaxF(mp + 2, ev.z);
    atomicMaxF(mp + 3, ev.w);
}

__global__ void edge_exp_kernel(const int* __restrict__ dst) {
    int e = blockIdx.x * blockDim.x + threadIdx.x;
    if (e >= NE) return;
    int d = dst[e];
    float4 ev = *(const float4*)(g_e + (size_t)e * NHD);
    float4 mv = *(const float4*)(g_m + d * NHD);
    float4 xv = make_float4(__expf(ev.x - mv.x), __expf(ev.y - mv.y),
                            __expf(ev.z - mv.z), __expf(ev.w - mv.w));
    *(float4*)(g_ex + (size_t)e * NHD) = xv;
    red4(g_den + d * NHD, xv.x, xv.y, xv.z, xv.w);
}

// warp per edge: scatter a * z[src] into rst[dst]
__global__ void edge_msg_kernel(const int* __restrict__ src, const int* __restrict__ dst,
                                const float* __restrict__ zin, float* __restrict__ rst) {
    int gt = blockIdx.x * blockDim.x + threadIdx.x;
    int e = gt >> 5;
    if (e >= NE) return;
    int lane = threadIdx.x & 31;
    int s = src[e], d = dst[e];
    float4 xv = *(const float4*)(g_ex + (size_t)e * NHD);
    float4 dv = *(const float4*)(g_den + d * NHD);
    float ax = xv.x / fmaxf(dv.x, 1e-9f);
    float ay = xv.y / fmaxf(dv.y, 1e-9f);
    float az = xv.z / fmaxf(dv.z, 1e-9f);
    float aw = xv.w / fmaxf(dv.w, 1e-9f);
    float a = (lane < 16) ? (lane < 8 ? ax : ay) : (lane < 24 ? az : aw);
    const float* zp = zin + (size_t)s * HIDD + lane * 8;
    float* rp = rst + (size_t)d * HIDD + lane * 8;
    float4 z0 = *(const float4*)zp;
    float4 z1 = *(const float4*)(zp + 4);
    red4(rp,     a * z0.x, a * z0.y, a * z0.z, a * z0.w);
    red4(rp + 4, a * z1.x, a * z1.y, a * z1.z, a * z1.w);
}

__global__ void gat_fin_kernel(const float* __restrict__ rst, const float* __restrict__ b,
                               float* __restrict__ hout) {
    int idx = blockIdx.x * blockDim.x + threadIdx.x;
    int i4 = idx * 4;
    if (i4 >= NN * HIDD) return;
    int c = i4 & (HIDD - 1);
    float4 r = *(const float4*)(rst + i4);
    float4 bb = *(const float4*)(b + c);
    float4 v;
    v.x = fmaxf(r.x + bb.x, 0.f);
    v.y = fmaxf(r.y + bb.y, 0.f);
    v.z = fmaxf(r.z + bb.z, 0.f);
    v.w = fmaxf(r.w + bb.w, 0.f);
    *(float4*)(hout + i4) = v;
}

// ---------------- concat + GIN pieces --------------------------------------
__global__ void concat_kernel(const float* __restrict__ h, const float* __restrict__ feats,
                              float* __restrict__ x) {
    int idx = blockIdx.x * blockDim.x + threadIdx.x;
    int i4 = idx * 4;
    if (i4 >= NN * CATF) return;
    int n = i4 / CATF;
    int c = i4 % CATF;
    float4 v = (c < HIDD) ? *(const float4*)(h + (size_t)n * HIDD + c)
                          : *(const float4*)(feats + (size_t)n * FIN + (c - HIDD));
    *(float4*)(x + i4) = v;
}

__global__ void edge_agg_kernel(const float* __restrict__ hin, const int* __restrict__ src,
                                const int* __restrict__ dst, float* __restrict__ agg, int F) {
    int gt = blockIdx.x * blockDim.x + threadIdx.x;
    int e = gt >> 5;
    if (e >= NE) return;
    int lane = threadIdx.x & 31;
    int s = src[e], d = dst[e];
    const float* hp = hin + (size_t)s * F;
    float* ap = agg + (size_t)d * F;
    for (int f = lane * 4; f < F; f += 128) {
        float4 v = *(const float4*)(hp + f);
        red4(ap + f, v.x, v.y, v.z, v.w);
    }
}

__global__ void combine_kernel(const float* __restrict__ hin, const float* __restrict__ agg,
                               const float* __restrict__ epsp, float* __restrict__ xout, int n) {
    int idx = blockIdx.x * blockDim.x + threadIdx.x;
    int i4 = idx * 4;
    if (i4 >= n) return;
    float e = 1.f + epsp[0];
    float4 hv = *(const float4*)(hin + i4);
    float4 av = *(const float4*)(agg + i4);
    float4 v = make_float4(e * hv.x + av.x, e * hv.y + av.y, e * hv.z + av.z, e * hv.w + av.w);
    *(float4*)(xout + i4) = v;
}

__global__ void stats_kernel(const float* __restrict__ y) {
    int col = threadIdx.x;
    float s = 0.f, s2 = 0.f;
    for (int r = blockIdx.x; r < NN; r += gridDim.x) {
        float v = y[(size_t)r * HIDD + col];
        s += v; s2 += v * v;
    }
    atomicAdd(&g_stats[col], s);
    atomicAdd(&g_stats[HIDD + col], s2);
}

__global__ void bnfin_kernel(const float* __restrict__ g1, const float* __restrict__ be1) {
    int c = threadIdx.x;
    float inv = 1.f / (float)NN;
    float mu = g_stats[c] * inv;
    float var = g_stats[HIDD + c] * inv - mu * mu;
    float rstd = rsqrtf(var + 1e-5f);
    float sc = g1[c] * rstd;
    g_scale[c] = sc;
    g_shift[c] = be1[c] - mu * sc;
}

__global__ void bnrelu_kernel(float* __restrict__ y) {
    int idx = blockIdx.x * blockDim.x + threadIdx.x;
    int i4 = idx * 4;
    if (i4 >= NN * HIDD) return;
    int c = i4 & (HIDD - 1);
    float4 v = *(const float4*)(y + i4);
    float4 sc = *(const float4*)(g_scale + c);
    float4 sh = *(const float4*)(g_shift + c);
    v.x = fmaxf(v.x * sc.x + sh.x, 0.f);
    v.y = fmaxf(v.y * sc.y + sh.y, 0.f);
    v.z = fmaxf(v.z * sc.z + sh.z, 0.f);
    v.w = fmaxf(v.w * sc.w + sh.w, 0.f);
    *(float4*)(y + i4) = v;
}

__global__ void zero_kernel(float* __restrict__ p, int n) {
    int idx = blockIdx.x * blockDim.x + threadIdx.x;
    int i4 = idx * 4;
    if (i4 >= n) return;
    *(float4*)(p + i4) = make_float4(0.f, 0.f, 0.f, 0.f);
}

// ---------------- host orchestration ---------------------------------------
static inline int blk4(int n) { return (n / 4 + 255) / 256; }

static void gemm(const float* A, const float* W, const float* b, float* C,
                 int K, int relu, int ldc = HIDD, int coff = 0) {
    dim3 grid(HIDD / BN, (NN + BM - 1) / BM);
    gemm_kernel<<<grid, 256>>>(A, W, b, C, NN, K, HIDD, ldc, coff, relu);
}

static void run_gat(const float* z, const float* al, const float* ar, const float* b,
                    const int* s, const int* d, float* rst, float* hout) {
    elz_kernel<<<NN, 128>>>(z, al, ar);
    init_nh_kernel<<<(NN * NHD + 255) / 256, 256>>>();
    edge_max_kernel<<<(NE + 255) / 256, 256>>>(s, d);
    edge_exp_kernel<<<(NE + 255) / 256, 256>>>(d);
    zero_kernel<<<blk4(NN * HIDD), 256>>>(rst, NN * HIDD);
    edge_msg_kernel<<<(NE * 32 + 255) / 256, 256>>>(s, d, z, rst);
    gat_fin_kernel<<<blk4(NN * HIDD), 256>>>(rst, b, hout);
}

static void run_gin(const float* hin, int F, const int* s, const int* d,
                    const float* eps, const float* W1, const float* b1,
                    const float* g1, const float* be1, const float* W2, const float* b2,
                    float* agg, float* xbuf, float* ybuf, float* hout, float* statsp,
                    int ldc, int coff) {
    zero_kernel<<<blk4(NN * F), 256>>>(agg, NN * F);
    edge_agg_kernel<<<(NE * 32 + 255) / 256, 256>>>(hin, s, d, agg, F);
    combine_kernel<<<blk4(NN * F), 256>>>(hin, agg, eps, xbuf, NN * F);
    gemm(xbuf, W1, b1, ybuf, F, 0);
    zero_kernel<<<1, 128>>>(statsp, 2 * HIDD);
    stats_kernel<<<512, HIDD>>>(ybuf);
    bnfin_kernel<<<1, HIDD>>>(g1, be1);
    bnrelu_kernel<<<blk4(NN * HIDD), 256>>>(ybuf);
    gemm(ybuf, W2, b2, hout, HIDD, 1, ldc, coff);
}

extern "C" void kernel_launch(void* const* d_in, const int* in_sizes, int n_in,
                              void* d_out, int out_size) {
    const float* feats = (const float*)d_in[0];
    const int* src[2] = { (const int*)d_in[1], (const int*)d_in[3] };
    const int* dst[2] = { (const int*)d_in[2], (const int*)d_in[4] };
    const float* gat0_W   = (const float*)d_in[5];
    const float* gat0_al  = (const float*)d_in[6];
    const float* gat0_ar  = (const float*)d_in[7];
    const float* gat0_b   = (const float*)d_in[8];
    const float* gat1_W   = (const float*)d_in[9];
    const float* gat1_al  = (const float*)d_in[10];
    const float* gat1_ar  = (const float*)d_in[11];
    const float* gat1_b   = (const float*)d_in[12];
    const float* gin0_eps = (const float*)d_in[13];
    const float* gin0_W1  = (const float*)d_in[14];
    const float* gin0_b1  = (const float*)d_in[15];
    const float* gin0_g1  = (const float*)d_in[16];
    const float* gin0_be1 = (const float*)d_in[17];
    const float* gin0_W2  = (const float*)d_in[18];
    const float* gin0_b2  = (const float*)d_in[19];
    const float* gin1_eps = (const float*)d_in[20];
    const float* gin1_W1  = (const float*)d_in[21];
    const float* gin1_b1  = (const float*)d_in[22];
    const float* gin1_g1  = (const float*)d_in[23];
    const float* gin1_be1 = (const float*)d_in[24];
    const float* gin1_W2  = (const float*)d_in[25];
    const float* gin1_b2  = (const float*)d_in[26];
    float* out = (float*)d_out;

    float *z, *h, *x, *scr, *statsp;
    cudaGetSymbolAddress((void**)&z, g_z);
    cudaGetSymbolAddress((void**)&h, g_h);
    cudaGetSymbolAddress((void**)&x, g_x);
    cudaGetSymbolAddress((void**)&scr, g_scr);
    cudaGetSymbolAddress((void**)&statsp, g_stats);

    for (int t = 0; t < TTYP; t++) {
        // GAT layer 0: z = feats @ W
        gemm(feats, gat0_W + (size_t)t * FIN * HIDD, nullptr, z, FIN, 0);
        run_gat(z, gat0_al + t * NHD * DH, gat0_ar + t * NHD * DH,
                gat0_b + t * HIDD, src[t], dst[t], scr, h);
        // GAT layer 1
        gemm(h, gat1_W + (size_t)t * HIDD * HIDD, nullptr, z, HIDD, 0);
        run_gat(z, gat1_al + t * NHD * DH, gat1_ar + t * NHD * DH,
                gat1_b + t * HIDD, src[t], dst[t], scr, h);
        // skip-concat
        concat_kernel<<<blk4(NN * CATF), 256>>>(h, feats, x);
        // GIN layer 0 (F = 384)
        run_gin(x, CATF, src[t], dst[t], gin0_eps + t,
                gin0_W1 + (size_t)t * CATF * HIDD, gin0_b1 + t * HIDD,
                gin0_g1 + t * HIDD, gin0_be1 + t * HIDD,
                gin0_W2 + (size_t)t * HIDD * HIDD, gin0_b2 + t * HIDD,
                scr, x, z, h, statsp, HIDD, 0);
        // GIN layer 1 (F = 256) — final GEMM writes straight into the strided output
        run_gin(h, HIDD, src[t], dst[t], gin1_eps + t,
                gin1_W1 + (size_t)t * HIDD * HIDD, gin1_b1 + t * HIDD,
                gin1_g1 + t * HIDD, gin1_be1 + t * HIDD,
                gin1_W2 + (size_t)t * HIDD * HIDD, gin1_b2 + t * HIDD,
                scr, x, z, out, statsp, TTYP * HIDD, t * HIDD);
    }
}

// round 4
// speedup vs baseline: 1.5425x; 1.4164x over previous
#include <cuda_runtime.h>
#include <cuda_bf16.h>
#include <math.h>

#define NN   50000
#define FIN  128
#define HIDD 256
#define NHD  4
#define DH   64
#define NE   400000
#define CATF 384
#define TTYP 2

// ---------------- scratch (device globals; no allocation allowed) ----------
static __device__ float g_z  [(size_t)NN*HIDD];
static __device__ float g_h  [(size_t)NN*HIDD];
static __device__ float g_x  [(size_t)NN*CATF];
static __device__ float g_scr[(size_t)NN*CATF];   // rst (256-wide) / agg (F-wide)
static __device__ float g_el [NN*NHD];
static __device__ float g_er [NN*NHD];
static __device__ float g_m  [NN*NHD];
static __device__ float g_den[NN*NHD];
static __device__ float g_e  [(size_t)NE*NHD];
static __device__ float g_ex [(size_t)NE*NHD];
static __device__ float g_stats[2*HIDD];
static __device__ float g_scale[HIDD];
static __device__ float g_shift[HIDD];

// ---------------- helpers --------------------------------------------------
__device__ __forceinline__ void red4(float* p, float a, float b, float c, float d) {
    asm volatile("red.global.add.v4.f32 [%0], {%1,%2,%3,%4};"
                 :: "l"(p), "f"(a), "f"(b), "f"(c), "f"(d) : "memory");
}

__device__ __forceinline__ void atomicMaxF(float* addr, float value) {
    if (value >= 0.f) atomicMax((int*)addr, __float_as_int(value));
    else              atomicMin((unsigned int*)addr, __float_as_uint(value));
}

__device__ __forceinline__ float lrelu(float v) { return v >= 0.f ? v : 0.2f * v; }

__device__ __forceinline__ unsigned int pack2(__nv_bfloat16 a, __nv_bfloat16 b) {
    return (unsigned int)__bfloat16_as_ushort(a) |
           ((unsigned int)__bfloat16_as_ushort(b) << 16);
}

__device__ __forceinline__ void split_bf(float v, __nv_bfloat16& h, __nv_bfloat16& l) {
    h = __float2bfloat16_rn(v);
    l = __float2bfloat16_rn(v - __bfloat162float(h));
}

__device__ __forceinline__ void mma16816(float* c, const unsigned int* a, const unsigned int* b) {
    asm volatile(
        "mma.sync.aligned.m16n8k16.row.col.f32.bf16.bf16.f32 "
        "{%0,%1,%2,%3}, {%4,%5,%6,%7}, {%8,%9}, {%0,%1,%2,%3};"
        : "+f"(c[0]), "+f"(c[1]), "+f"(c[2]), "+f"(c[3])
        : "r"(a[0]), "r"(a[1]), "r"(a[2]), "r"(a[3]), "r"(b[0]), "r"(b[1]));
}

// ---------------- tensor-core GEMM: C = act(A[M,K] @ W[K,256] + bias) ------
// bf16 hi/lo split (3 MMA passes) for fp32-grade accuracy.
// Block tile 128x128, 8 warps of 64x32, BK=32. SMEM stride 20 words (40 bf16).
#define SSTR 20
__global__ __launch_bounds__(256, 2)
void gemm_tc_kernel(const float* __restrict__ A, const float* __restrict__ W,
                    const float* __restrict__ bias, float* __restrict__ C,
                    int M, int K, int Nout, int ldc, int coff, int relu_flag) {
    __shared__ unsigned int AH[128 * SSTR];
    __shared__ unsigned int AL[128 * SSTR];
    __shared__ unsigned int BH[128 * SSTR];
    __shared__ unsigned int BL[128 * SSTR];

    int tid = threadIdx.x;
    int lane = tid & 31, wid = tid >> 5;
    int lm = lane >> 2, lc = lane & 3;
    int m0 = (wid >> 2) * 64;
    int n0w = (wid & 3) * 32;
    int rowBase = blockIdx.y * 128;
    int colBase = blockIdx.x * 128;

    float acc[16][4];
#pragma unroll
    for (int i = 0; i < 16; i++)
#pragma unroll
        for (int j = 0; j < 4; j++) acc[i][j] = 0.f;

    // B staging mapping: thread -> (n, k-half)
    int bn = tid & 127;
    int bkh = (tid >> 7) * 16;

    int nkt = K / 32;
    for (int kt = 0; kt < nkt; kt++) {
        int k0 = kt * 32;
        // ---- stage A tile (128 x 32 fp32 -> bf16 hi/lo) ----
#pragma unroll
        for (int i = 0; i < 4; i++) {
            int pos = tid + i * 256;
            int m = pos >> 3;
            int k = (pos & 7) * 4;
            int row = rowBase + m;
            float4 v = make_float4(0.f, 0.f, 0.f, 0.f);
            if (row < M) v = *(const float4*)(A + (size_t)row * K + k0 + k);
            __nv_bfloat16 h0, h1, h2, h3, l0, l1, l2, l3;
            split_bf(v.x, h0, l0); split_bf(v.y, h1, l1);
            split_bf(v.z, h2, l2); split_bf(v.w, h3, l3);
            int w = m * SSTR + (k >> 1);
            AH[w]     = pack2(h0, h1);
            AH[w + 1] = pack2(h2, h3);
            AL[w]     = pack2(l0, l1);
            AL[w + 1] = pack2(l2, l3);
        }
        // ---- stage B tile (32 x 128 fp32 -> transposed bf16 hi/lo) ----
        {
            float vb[16];
            const float* wp = W + (size_t)(k0 + bkh) * Nout + colBase + bn;
#pragma unroll
            for (int i = 0; i < 16; i++) vb[i] = wp[(size_t)i * Nout];
#pragma unroll
            for (int q = 0; q < 4; q++) {
                __nv_bfloat16 h0, h1, h2, h3, l0, l1, l2, l3;
                split_bf(vb[q * 4 + 0], h0, l0); split_bf(vb[q * 4 + 1], h1, l1);
                split_bf(vb[q * 4 + 2], h2, l2); split_bf(vb[q * 4 + 3], h3, l3);
                int w = bn * SSTR + ((bkh + q * 4) >> 1);
                BH[w]     = pack2(h0, h1);
                BH[w + 1] = pack2(h2, h3);
                BL[w]     = pack2(l0, l1);
                BL[w + 1] = pack2(l2, l3);
            }
        }
        __syncthreads();
        // ---- compute: two k16 steps ----
#pragma unroll
        for (int kk = 0; kk < 2; kk++) {
            int kw = kk * 8;
            unsigned int ah[4][4], al[4][4], bh[4][2], bl[4][2];
#pragma unroll
            for (int mi = 0; mi < 4; mi++) {
                int r = m0 + mi * 16 + lm;
                int w0 = r * SSTR + kw + lc;
                int w1 = (r + 8) * SSTR + kw + lc;
                ah[mi][0] = AH[w0]; ah[mi][1] = AH[w1];
                ah[mi][2] = AH[w0 + 4]; ah[mi][3] = AH[w1 + 4];
                al[mi][0] = AL[w0]; al[mi][1] = AL[w1];
                al[mi][2] = AL[w0 + 4]; al[mi][3] = AL[w1 + 4];
            }
#pragma unroll
            for (int ni = 0; ni < 4; ni++) {
                int n = n0w + ni * 8 + lm;
                int w0 = n * SSTR + kw + lc;
                bh[ni][0] = BH[w0]; bh[ni][1] = BH[w0 + 4];
                bl[ni][0] = BL[w0]; bl[ni][1] = BL[w0 + 4];
            }
#pragma unroll
            for (int mi = 0; mi < 4; mi++)
#pragma unroll
                for (int ni = 0; ni < 4; ni++) {
                    float* c = acc[mi * 4 + ni];
                    mma16816(c, ah[mi], bh[ni]);
                    mma16816(c, ah[mi], bl[ni]);
                    mma16816(c, al[mi], bh[ni]);
                }
        }
        __syncthreads();
    }

    // ---- epilogue ----
#pragma unroll
    for (int mi = 0; mi < 4; mi++) {
#pragma unroll
        for (int ni = 0; ni < 4; ni++) {
            float* c = acc[mi * 4 + ni];
            int r0 = rowBase + m0 + mi * 16 + lm;
            int r1 = r0 + 8;
            int col = colBase + n0w + ni * 8 + lc * 2;
            float b0 = bias ? bias[col] : 0.f;
            float b1 = bias ? bias[col + 1] : 0.f;
            float v0 = c[0] + b0, v1 = c[1] + b1;
            float v2 = c[2] + b0, v3 = c[3] + b1;
            if (relu_flag) {
                v0 = fmaxf(v0, 0.f); v1 = fmaxf(v1, 0.f);
                v2 = fmaxf(v2, 0.f); v3 = fmaxf(v3, 0.f);
            }
            if (r0 < M) *(float2*)(C + (size_t)r0 * ldc + coff + col) = make_float2(v0, v1);
            if (r1 < M) *(float2*)(C + (size_t)r1 * ldc + coff + col) = make_float2(v2, v3);
        }
    }
}

// ---------------- GAT pieces -----------------------------------------------
__global__ void elz_kernel(const float* __restrict__ z,
                           const float* __restrict__ al, const float* __restrict__ ar) {
    int n = blockIdx.x;
    int w = threadIdx.x >> 5;
    int lane = threadIdx.x & 31;
    const float* zp = z + (size_t)n * HIDD + w * DH;
    float z0 = zp[lane], z1 = zp[lane + 32];
    float a0 = al[w * DH + lane], a1 = al[w * DH + lane + 32];
    float b0 = ar[w * DH + lane], b1 = ar[w * DH + lane + 32];
    float el = z0 * a0 + z1 * a1;
    float er = z0 * b0 + z1 * b1;
#pragma unroll
    for (int off = 16; off; off >>= 1) {
        el += __shfl_down_sync(0xffffffffu, el, off);
        er += __shfl_down_sync(0xffffffffu, er, off);
    }
    if (lane == 0) { g_el[n * NHD + w] = el; g_er[n * NHD + w] = er; }
}

__global__ void init_nh_kernel() {
    int i = blockIdx.x * blockDim.x + threadIdx.x;
    if (i < NN * NHD) { g_m[i] = -INFINITY; g_den[i] = 0.f; }
}

__global__ void edge_max_kernel(const int* __restrict__ src, const int* __restrict__ dst) {
    int e = blockIdx.x * blockDim.x + threadIdx.x;
    if (e >= NE) return;
    int s = src[e], d = dst[e];
    float4 elv = *(const float4*)(g_el + s * NHD);
    float4 erv = *(const float4*)(g_er + d * NHD);
    float4 ev;
    ev.x = lrelu(elv.x + erv.x);
    ev.y = lrelu(elv.y + erv.y);
    ev.z = lrelu(elv.z + erv.z);
    ev.w = lrelu(elv.w + erv.w);
    *(float4*)(g_e + (size_t)e * NHD) = ev;
    float* mp = g_m + d * NHD;
    atomicMaxF(mp + 0, ev.x);
    atomicMaxF(mp + 1, ev.y);
    atomicMaxF(mp + 2, ev.z);
    atomicMaxF(mp + 3, ev.w);
}

__global__ void edge_exp_kernel(const int* __restrict__ dst) {
    int e = blockIdx.x * blockDim.x + threadIdx.x;
    if (e >= NE) return;
    int d = dst[e];
    float4 ev = *(const float4*)(g_e + (size_t)e * NHD);
    float4 mv = *(const float4*)(g_m + d * NHD);
    float4 xv = make_float4(__expf(ev.x - mv.x), __expf(ev.y - mv.y),
                            __expf(ev.z - mv.z), __expf(ev.w - mv.w));
    *(float4*)(g_ex + (size_t)e * NHD) = xv;
    red4(g_den + d * NHD, xv.x, xv.y, xv.z, xv.w);
}

// warp per edge: scatter a * z[src] into rst[dst]
__global__ void edge_msg_kernel(const int* __restrict__ src, const int* __restrict__ dst,
                                const float* __restrict__ zin, float* __restrict__ rst) {
    int gt = blockIdx.x * blockDim.x + threadIdx.x;
    int e = gt >> 5;
    if (e >= NE) return;
    int lane = threadIdx.x & 31;
    int s = src[e], d = dst[e];
    float4 xv = *(const float4*)(g_ex + (size_t)e * NHD);
    float4 dv = *(const float4*)(g_den + d * NHD);
    float ax = xv.x / fmaxf(dv.x, 1e-9f);
    float ay = xv.y / fmaxf(dv.y, 1e-9f);
    float az = xv.z / fmaxf(dv.z, 1e-9f);
    float aw = xv.w / fmaxf(dv.w, 1e-9f);
    float a = (lane < 16) ? (lane < 8 ? ax : ay) : (lane < 24 ? az : aw);
    const float* zp = zin + (size_t)s * HIDD + lane * 8;
    float* rp = rst + (size_t)d * HIDD + lane * 8;
    float4 z0 = *(const float4*)zp;
    float4 z1 = *(const float4*)(zp + 4);
    red4(rp,     a * z0.x, a * z0.y, a * z0.z, a * z0.w);
    red4(rp + 4, a * z1.x, a * z1.y, a * z1.z, a * z1.w);
}

__global__ void gat_fin_kernel(const float* __restrict__ rst, const float* __restrict__ b,
                               float* __restrict__ hout) {
    int idx = blockIdx.x * blockDim.x + threadIdx.x;
    int i4 = idx * 4;
    if (i4 >= NN * HIDD) return;
    int c = i4 & (HIDD - 1);
    float4 r = *(const float4*)(rst + i4);
    float4 bb = *(const float4*)(b + c);
    float4 v;
    v.x = fmaxf(r.x + bb.x, 0.f);
    v.y = fmaxf(r.y + bb.y, 0.f);
    v.z = fmaxf(r.z + bb.z, 0.f);
    v.w = fmaxf(r.w + bb.w, 0.f);
    *(float4*)(hout + i4) = v;
}

// ---------------- concat + GIN pieces --------------------------------------
__global__ void concat_kernel(const float* __restrict__ h, const float* __restrict__ feats,
                              float* __restrict__ x) {
    int idx = blockIdx.x * blockDim.x + threadIdx.x;
    int i4 = idx * 4;
    if (i4 >= NN * CATF) return;
    int n = i4 / CATF;
    int c = i4 % CATF;
    float4 v = (c < HIDD) ? *(const float4*)(h + (size_t)n * HIDD + c)
                          : *(const float4*)(feats + (size_t)n * FIN + (c - HIDD));
    *(float4*)(x + i4) = v;
}

__global__ void edge_agg_kernel(const float* __restrict__ hin, const int* __restrict__ src,
                                const int* __restrict__ dst, float* __restrict__ agg, int F) {
    int gt = blockIdx.x * blockDim.x + threadIdx.x;
    int e = gt >> 5;
    if (e >= NE) return;
    int lane = threadIdx.x & 31;
    int s = src[e], d = dst[e];
    const float* hp = hin + (size_t)s * F;
    float* ap = agg + (size_t)d * F;
    for (int f = lane * 4; f < F; f += 128) {
        float4 v = *(const float4*)(hp + f);
        red4(ap + f, v.x, v.y, v.z, v.w);
    }
}

__global__ void combine_kernel(const float* __restrict__ hin, const float* __restrict__ agg,
                               const float* __restrict__ epsp, float* __restrict__ xout, int n) {
    int idx = blockIdx.x * blockDim.x + threadIdx.x;
    int i4 = idx * 4;
    if (i4 >= n) return;
    float e = 1.f + epsp[0];
    float4 hv = *(const float4*)(hin + i4);
    float4 av = *(const float4*)(agg + i4);
    float4 v = make_float4(e * hv.x + av.x, e * hv.y + av.y, e * hv.z + av.z, e * hv.w + av.w);
    *(float4*)(xout + i4) = v;
}

__global__ void stats_kernel(const float* __restrict__ y) {
    int col = threadIdx.x;
    float s = 0.f, s2 = 0.f;
    for (int r = blockIdx.x; r < NN; r += gridDim.x) {
        float v = y[(size_t)r * HIDD + col];
        s += v; s2 += v * v;
    }
    atomicAdd(&g_stats[col], s);
    atomicAdd(&g_stats[HIDD + col], s2);
}

__global__ void bnfin_kernel(const float* __restrict__ g1, const float* __restrict__ be1) {
    int c = threadIdx.x;
    float inv = 1.f / (float)NN;
    float mu = g_stats[c] * inv;
    float var = g_stats[HIDD + c] * inv - mu * mu;
    float rstd = rsqrtf(var + 1e-5f);
    float sc = g1[c] * rstd;
    g_scale[c] = sc;
    g_shift[c] = be1[c] - mu * sc;
}

__global__ void bnrelu_kernel(float* __restrict__ y) {
    int idx = blockIdx.x * blockDim.x + threadIdx.x;
    int i4 = idx * 4;
    if (i4 >= NN * HIDD) return;
    int c = i4 & (HIDD - 1);
    float4 v = *(const float4*)(y + i4);
    float4 sc = *(const float4*)(g_scale + c);
    float4 sh = *(const float4*)(g_shift + c);
    v.x = fmaxf(v.x * sc.x + sh.x, 0.f);
    v.y = fmaxf(v.y * sc.y + sh.y, 0.f);
    v.z = fmaxf(v.z * sc.z + sh.z, 0.f);
    v.w = fmaxf(v.w * sc.w + sh.w, 0.f);
    *(float4*)(y + i4) = v;
}

__global__ void zero_kernel(float* __restrict__ p, int n) {
    int idx = blockIdx.x * blockDim.x + threadIdx.x;
    int i4 = idx * 4;
    if (i4 >= n) return;
    *(float4*)(p + i4) = make_float4(0.f, 0.f, 0.f, 0.f);
}

// ---------------- host orchestration ---------------------------------------
static inline int blk4(int n) { return (n / 4 + 255) / 256; }

static void gemm(const float* A, const float* W, const float* b, float* C,
                 int K, int relu, int ldc = HIDD, int coff = 0) {
    dim3 grid(HIDD / 128, (NN + 127) / 128);
    gemm_tc_kernel<<<grid, 256>>>(A, W, b, C, NN, K, HIDD, ldc, coff, relu);
}

static void run_gat(const float* z, const float* al, const float* ar, const float* b,
                    const int* s, const int* d, float* rst, float* hout) {
    elz_kernel<<<NN, 128>>>(z, al, ar);
    init_nh_kernel<<<(NN * NHD + 255) / 256, 256>>>();
    edge_max_kernel<<<(NE + 255) / 256, 256>>>(s, d);
    edge_exp_kernel<<<(NE + 255) / 256, 256>>>(d);
    zero_kernel<<<blk4(NN * HIDD), 256>>>(rst, NN * HIDD);
    edge_msg_kernel<<<(NE * 32 + 255) / 256, 256>>>(s, d, z, rst);
    gat_fin_kernel<<<blk4(NN * HIDD), 256>>>(rst, b, hout);
}

static void run_gin(const float* hin, int F, const int* s, const int* d,
                    const float* eps, const float* W1, const float* b1,
                    const float* g1, const float* be1, const float* W2, const float* b2,
                    float* agg, float* xbuf, float* ybuf, float* hout, float* statsp,
                    int ldc, int coff) {
    zero_kernel<<<blk4(NN * F), 256>>>(agg, NN * F);
    edge_agg_kernel<<<(NE * 32 + 255) / 256, 256>>>(hin, s, d, agg, F);
    combine_kernel<<<blk4(NN * F), 256>>>(hin, agg, eps, xbuf, NN * F);
    gemm(xbuf, W1, b1, ybuf, F, 0);
    zero_kernel<<<1, 128>>>(statsp, 2 * HIDD);
    stats_kernel<<<512, HIDD>>>(ybuf);
    bnfin_kernel<<<1, HIDD>>>(g1, be1);
    bnrelu_kernel<<<blk4(NN * HIDD), 256>>>(ybuf);
    gemm(ybuf, W2, b2, hout, HIDD, 1, ldc, coff);
}

extern "C" void kernel_launch(void* const* d_in, const int* in_sizes, int n_in,
                              void* d_out, int out_size) {
    const float* feats = (const float*)d_in[0];
    const int* src[2] = { (const int*)d_in[1], (const int*)d_in[3] };
    const int* dst[2] = { (const int*)d_in[2], (const int*)d_in[4] };
    const float* gat0_W   = (const float*)d_in[5];
    const float* gat0_al  = (const float*)d_in[6];
    const float* gat0_ar  = (const float*)d_in[7];
    const float* gat0_b   = (const float*)d_in[8];
    const float* gat1_W   = (const float*)d_in[9];
    const float* gat1_al  = (const float*)d_in[10];
    const float* gat1_ar  = (const float*)d_in[11];
    const float* gat1_b   = (const float*)d_in[12];
    const float* gin0_eps = (const float*)d_in[13];
    const float* gin0_W1  = (const float*)d_in[14];
    const float* gin0_b1  = (const float*)d_in[15];
    const float* gin0_g1  = (const float*)d_in[16];
    const float* gin0_be1 = (const float*)d_in[17];
    const float* gin0_W2  = (const float*)d_in[18];
    const float* gin0_b2  = (const float*)d_in[19];
    const float* gin1_eps = (const float*)d_in[20];
    const float* gin1_W1  = (const float*)d_in[21];
    const float* gin1_b1  = (const float*)d_in[22];
    const float* gin1_g1  = (const float*)d_in[23];
    const float* gin1_be1 = (const float*)d_in[24];
    const float* gin1_W2  = (const float*)d_in[25];
    const float* gin1_b2  = (const float*)d_in[26];
    float* out = (float*)d_out;

    float *z, *h, *x, *scr, *statsp;
    cudaGetSymbolAddress((void**)&z, g_z);
    cudaGetSymbolAddress((void**)&h, g_h);
    cudaGetSymbolAddress((void**)&x, g_x);
    cudaGetSymbolAddress((void**)&scr, g_scr);
    cudaGetSymbolAddress((void**)&statsp, g_stats);

    for (int t = 0; t < TTYP; t++) {
        // GAT layer 0: z = feats @ W
        gemm(feats, gat0_W + (size_t)t * FIN * HIDD, nullptr, z, FIN, 0);
        run_gat(z, gat0_al + t * NHD * DH, gat0_ar + t * NHD * DH,
                gat0_b + t * HIDD, src[t], dst[t], scr, h);
        // GAT layer 1
        gemm(h, gat1_W + (size_t)t * HIDD * HIDD, nullptr, z, HIDD, 0);
        run_gat(z, gat1_al + t * NHD * DH, gat1_ar + t * NHD * DH,
                gat1_b + t * HIDD, src[t], dst[t], scr, h);
        // skip-concat
        concat_kernel<<<blk4(NN * CATF), 256>>>(h, feats, x);
        // GIN layer 0 (F = 384)
        run_gin(x, CATF, src[t], dst[t], gin0_eps + t,
                gin0_W1 + (size_t)t * CATF * HIDD, gin0_b1 + t * HIDD,
                gin0_g1 + t * HIDD, gin0_be1 + t * HIDD,
                gin0_W2 + (size_t)t * HIDD * HIDD, gin0_b2 + t * HIDD,
                scr, x, z, h, statsp, HIDD, 0);
        // GIN layer 1 (F = 256) — final GEMM writes straight into the strided output
        run_gin(h, HIDD, src[t], dst[t], gin1_eps + t,
                gin1_W1 + (size_t)t * HIDD * HIDD, gin1_b1 + t * HIDD,
                gin1_g1 + t * HIDD, gin1_be1 + t * HIDD,
                gin1_W2 + (size_t)t * HIDD * HIDD, gin1_b2 + t * HIDD,
                scr, x, z, out, statsp, TTYP * HIDD, t * HIDD);
    }
}